// round 1
// baseline (speedup 1.0000x reference)
#include <cuda_runtime.h>

// Problem constants (fixed by the reference)
#define BATCH 4
#define SEQ   2048
#define EMB   1024
#define HDIM  1024

// Static device scratch (allocation-free rule: __device__ globals only)
__device__ float g_Q[BATCH * SEQ * HDIM];
__device__ float g_K[BATCH * SEQ * HDIM];
__device__ float g_V[BATCH * SEQ * HDIM];
__device__ float g_P[(size_t)BATCH * SEQ * SEQ];  // scores -> probabilities (in place)

// ---------------------------------------------------------------------------
// Kernel 1: fused QKV projection.  C = X * W^T + b  (NT GEMM)
//   X:  [M=8192, K=1024] row-major
//   W:  [N=1024, K=1024] row-major (contract over K)
// grid: (N/128, M/128, 3)   z selects (Wq,bq,gQ) / (Wk,bk,gK) / (Wv,bv,gV)
// ---------------------------------------------------------------------------
__global__ __launch_bounds__(256) void qkv_kernel(
    const float* __restrict__ X,
    const float* __restrict__ Wq, const float* __restrict__ bq,
    const float* __restrict__ Wk, const float* __restrict__ bk,
    const float* __restrict__ Wv, const float* __restrict__ bv)
{
    const int K = EMB;
    const int N = HDIM;

    const float* W;
    const float* bias;
    float* out;
    if (blockIdx.z == 0)      { W = Wq; bias = bq; out = g_Q; }
    else if (blockIdx.z == 1) { W = Wk; bias = bk; out = g_K; }
    else                      { W = Wv; bias = bv; out = g_V; }

    __shared__ __align__(16) float As[16][128];
    __shared__ __align__(16) float Bs[16][128];

    const int tid = threadIdx.x;
    const int m0 = blockIdx.y * 128;
    const int n0 = blockIdx.x * 128;
    const int ty = tid >> 4;   // 0..15
    const int tx = tid & 15;   // 0..15

    float acc[8][8];
#pragma unroll
    for (int i = 0; i < 8; i++)
#pragma unroll
        for (int j = 0; j < 8; j++) acc[i][j] = 0.f;

    for (int k0 = 0; k0 < K; k0 += 16) {
        // Load A tile (128 rows x 16 k), transposed into As[k][m]
#pragma unroll
        for (int it = 0; it < 2; it++) {
            int idx = tid + it * 256;          // 0..511 float4 slots
            int row = idx >> 2;
            int c4  = (idx & 3) * 4;
            float4 v = *(const float4*)&X[(size_t)(m0 + row) * K + k0 + c4];
            As[c4 + 0][row] = v.x; As[c4 + 1][row] = v.y;
            As[c4 + 2][row] = v.z; As[c4 + 3][row] = v.w;
        }
        // Load B tile (128 n-rows x 16 k), transposed into Bs[k][n]
#pragma unroll
        for (int it = 0; it < 2; it++) {
            int idx = tid + it * 256;
            int row = idx >> 2;
            int c4  = (idx & 3) * 4;
            float4 v = *(const float4*)&W[(size_t)(n0 + row) * K + k0 + c4];
            Bs[c4 + 0][row] = v.x; Bs[c4 + 1][row] = v.y;
            Bs[c4 + 2][row] = v.z; Bs[c4 + 3][row] = v.w;
        }
        __syncthreads();

#pragma unroll
        for (int kk = 0; kk < 16; kk++) {
            float4 a0 = *(const float4*)&As[kk][ty * 8];
            float4 a1 = *(const float4*)&As[kk][ty * 8 + 4];
            float4 b0 = *(const float4*)&Bs[kk][tx * 8];
            float4 b1 = *(const float4*)&Bs[kk][tx * 8 + 4];
            float a[8] = {a0.x, a0.y, a0.z, a0.w, a1.x, a1.y, a1.z, a1.w};
            float b[8] = {b0.x, b0.y, b0.z, b0.w, b1.x, b1.y, b1.z, b1.w};
#pragma unroll
            for (int i = 0; i < 8; i++)
#pragma unroll
                for (int j = 0; j < 8; j++) acc[i][j] += a[i] * b[j];
        }
        __syncthreads();
    }

    float4 bias_lo = *(const float4*)&bias[n0 + tx * 8];
    float4 bias_hi = *(const float4*)&bias[n0 + tx * 8 + 4];
    float bb[8] = {bias_lo.x, bias_lo.y, bias_lo.z, bias_lo.w,
                   bias_hi.x, bias_hi.y, bias_hi.z, bias_hi.w};
#pragma unroll
    for (int i = 0; i < 8; i++) {
        float* crow = &out[(size_t)(m0 + ty * 8 + i) * N + n0 + tx * 8];
        float4 v0 = {acc[i][0] + bb[0], acc[i][1] + bb[1], acc[i][2] + bb[2], acc[i][3] + bb[3]};
        float4 v1 = {acc[i][4] + bb[4], acc[i][5] + bb[5], acc[i][6] + bb[6], acc[i][7] + bb[7]};
        *(float4*)&crow[0] = v0;
        *(float4*)&crow[4] = v1;
    }
}

// ---------------------------------------------------------------------------
// Kernel 2: causal scores.  S[q,k] = scale * dot(Q[q,:], K[k,:])   (NT GEMM)
// grid: (SEQ/128 k-tiles, SEQ/128 q-tiles, BATCH); skip k_tile > q_tile.
// ---------------------------------------------------------------------------
__global__ __launch_bounds__(256) void scores_kernel()
{
    const int bxk = blockIdx.x;  // k tile
    const int byq = blockIdx.y;  // q tile
    if (bxk > byq) return;       // fully masked tile
    const int b = blockIdx.z;

    const float* A = g_Q + (size_t)b * SEQ * HDIM;
    const float* Bm = g_K + (size_t)b * SEQ * HDIM;
    float* C = g_P + (size_t)b * SEQ * SEQ;

    __shared__ __align__(16) float As[16][128];
    __shared__ __align__(16) float Bs[16][128];

    const int tid = threadIdx.x;
    const int m0 = byq * 128;
    const int n0 = bxk * 128;
    const int ty = tid >> 4;
    const int tx = tid & 15;

    float acc[8][8];
#pragma unroll
    for (int i = 0; i < 8; i++)
#pragma unroll
        for (int j = 0; j < 8; j++) acc[i][j] = 0.f;

    for (int k0 = 0; k0 < HDIM; k0 += 16) {
#pragma unroll
        for (int it = 0; it < 2; it++) {
            int idx = tid + it * 256;
            int row = idx >> 2;
            int c4  = (idx & 3) * 4;
            float4 v = *(const float4*)&A[(size_t)(m0 + row) * HDIM + k0 + c4];
            As[c4 + 0][row] = v.x; As[c4 + 1][row] = v.y;
            As[c4 + 2][row] = v.z; As[c4 + 3][row] = v.w;
        }
#pragma unroll
        for (int it = 0; it < 2; it++) {
            int idx = tid + it * 256;
            int row = idx >> 2;
            int c4  = (idx & 3) * 4;
            float4 v = *(const float4*)&Bm[(size_t)(n0 + row) * HDIM + k0 + c4];
            Bs[c4 + 0][row] = v.x; Bs[c4 + 1][row] = v.y;
            Bs[c4 + 2][row] = v.z; Bs[c4 + 3][row] = v.w;
        }
        __syncthreads();

#pragma unroll
        for (int kk = 0; kk < 16; kk++) {
            float4 a0 = *(const float4*)&As[kk][ty * 8];
            float4 a1 = *(const float4*)&As[kk][ty * 8 + 4];
            float4 b0 = *(const float4*)&Bs[kk][tx * 8];
            float4 b1 = *(const float4*)&Bs[kk][tx * 8 + 4];
            float a[8] = {a0.x, a0.y, a0.z, a0.w, a1.x, a1.y, a1.z, a1.w};
            float b[8] = {b0.x, b0.y, b0.z, b0.w, b1.x, b1.y, b1.z, b1.w};
#pragma unroll
            for (int i = 0; i < 8; i++)
#pragma unroll
                for (int j = 0; j < 8; j++) acc[i][j] += a[i] * b[j];
        }
        __syncthreads();
    }

    const float scale = 0.03125f;  // 1/sqrt(1024)
#pragma unroll
    for (int i = 0; i < 8; i++) {
        float* crow = &C[(size_t)(m0 + ty * 8 + i) * SEQ + n0 + tx * 8];
        float4 v0 = {acc[i][0] * scale, acc[i][1] * scale, acc[i][2] * scale, acc[i][3] * scale};
        float4 v1 = {acc[i][4] * scale, acc[i][5] * scale, acc[i][6] * scale, acc[i][7] * scale};
        *(float4*)&crow[0] = v0;
        *(float4*)&crow[4] = v1;
    }
}

// ---------------------------------------------------------------------------
// Kernel 3: causal softmax, one block per (b,q) row.
// Only k <= q is valid; masked tail is written as exact 0.
// ---------------------------------------------------------------------------
__global__ __launch_bounds__(256) void softmax_kernel()
{
    const int row = blockIdx.x;          // 0 .. BATCH*SEQ-1
    const int q   = row & (SEQ - 1);
    float* p = g_P + (size_t)row * SEQ;
    const int valid = q + 1;
    const int tid = threadIdx.x;

    __shared__ float red[256];

    float mx = -3.0e38f;
    for (int i = tid; i < valid; i += 256) mx = fmaxf(mx, p[i]);
    red[tid] = mx;
    __syncthreads();
    for (int s = 128; s > 0; s >>= 1) {
        if (tid < s) red[tid] = fmaxf(red[tid], red[tid + s]);
        __syncthreads();
    }
    mx = red[0];
    __syncthreads();

    float sum = 0.f;
    for (int i = tid; i < valid; i += 256) {
        float e = __expf(p[i] - mx);
        p[i] = e;
        sum += e;
    }
    red[tid] = sum;
    __syncthreads();
    for (int s = 128; s > 0; s >>= 1) {
        if (tid < s) red[tid] += red[tid + s];
        __syncthreads();
    }
    const float inv = 1.0f / red[0];

    for (int i = tid; i < SEQ; i += 256) {
        if (i < valid) p[i] *= inv;
        else           p[i] = 0.f;
    }
}

// ---------------------------------------------------------------------------
// Kernel 4: O = P * V   (NN GEMM), causal: K-loop bounded by q_tile_end.
//   P: [SEQ, SEQ] row-major, V: [SEQ, HDIM] row-major.
// grid: (HDIM/128, SEQ/128, BATCH)
// ---------------------------------------------------------------------------
__global__ __launch_bounds__(256) void pv_kernel(float* __restrict__ O)
{
    const int b = blockIdx.z;
    const float* A = g_P + (size_t)b * SEQ * SEQ;
    const float* V = g_V + (size_t)b * SEQ * HDIM;
    float* C = O + (size_t)b * SEQ * HDIM;

    __shared__ __align__(16) float As[16][128];
    __shared__ __align__(16) float Bs[16][128];

    const int tid = threadIdx.x;
    const int m0 = blockIdx.y * 128;
    const int n0 = blockIdx.x * 128;
    const int ty = tid >> 4;
    const int tx = tid & 15;
    const int kend = m0 + 128;   // causal bound (P zero beyond diagonal handles the rest)

    float acc[8][8];
#pragma unroll
    for (int i = 0; i < 8; i++)
#pragma unroll
        for (int j = 0; j < 8; j++) acc[i][j] = 0.f;

    for (int k0 = 0; k0 < kend; k0 += 16) {
        // A tile (P): rows m, k contiguous -> transpose into As[k][m]
#pragma unroll
        for (int it = 0; it < 2; it++) {
            int idx = tid + it * 256;
            int row = idx >> 2;
            int c4  = (idx & 3) * 4;
            float4 v = *(const float4*)&A[(size_t)(m0 + row) * SEQ + k0 + c4];
            As[c4 + 0][row] = v.x; As[c4 + 1][row] = v.y;
            As[c4 + 2][row] = v.z; As[c4 + 3][row] = v.w;
        }
        // B tile (V): 16 k-rows x 128 n, n contiguous -> direct store
#pragma unroll
        for (int it = 0; it < 2; it++) {
            int idx = tid + it * 256;        // 0..511
            int row = idx >> 5;              // 0..15
            int c4  = idx & 31;              // float4 column
            float4 v = *(const float4*)&V[(size_t)(k0 + row) * HDIM + n0 + c4 * 4];
            *(float4*)&Bs[row][c4 * 4] = v;
        }
        __syncthreads();

#pragma unroll
        for (int kk = 0; kk < 16; kk++) {
            float4 a0 = *(const float4*)&As[kk][ty * 8];
            float4 a1 = *(const float4*)&As[kk][ty * 8 + 4];
            float4 b0 = *(const float4*)&Bs[kk][tx * 8];
            float4 b1 = *(const float4*)&Bs[kk][tx * 8 + 4];
            float a[8] = {a0.x, a0.y, a0.z, a0.w, a1.x, a1.y, a1.z, a1.w};
            float b[8] = {b0.x, b0.y, b0.z, b0.w, b1.x, b1.y, b1.z, b1.w};
#pragma unroll
            for (int i = 0; i < 8; i++)
#pragma unroll
                for (int j = 0; j < 8; j++) acc[i][j] += a[i] * b[j];
        }
        __syncthreads();
    }

#pragma unroll
    for (int i = 0; i < 8; i++) {
        float* crow = &C[(size_t)(m0 + ty * 8 + i) * HDIM + n0 + tx * 8];
        float4 v0 = {acc[i][0], acc[i][1], acc[i][2], acc[i][3]};
        float4 v1 = {acc[i][4], acc[i][5], acc[i][6], acc[i][7]};
        *(float4*)&crow[0] = v0;
        *(float4*)&crow[4] = v1;
    }
}

// ---------------------------------------------------------------------------
// Launch: 4 kernels, graph-capturable, no allocations, no syncs.
// Input order per metadata: X, Wq, bq, Wk, bk, Wv, bv, mask (mask ignored:
// causality is static).
// ---------------------------------------------------------------------------
extern "C" void kernel_launch(void* const* d_in, const int* in_sizes, int n_in,
                              void* d_out, int out_size)
{
    (void)in_sizes; (void)n_in; (void)out_size;
    const float* X  = (const float*)d_in[0];
    const float* Wq = (const float*)d_in[1];
    const float* bq = (const float*)d_in[2];
    const float* Wk = (const float*)d_in[3];
    const float* bk = (const float*)d_in[4];
    const float* Wv = (const float*)d_in[5];
    const float* bv = (const float*)d_in[6];
    float* out = (float*)d_out;

    dim3 gQKV(HDIM / 128, (BATCH * SEQ) / 128, 3);
    qkv_kernel<<<gQKV, 256>>>(X, Wq, bq, Wk, bk, Wv, bv);

    dim3 gS(SEQ / 128, SEQ / 128, BATCH);
    scores_kernel<<<gS, 256>>>();

    softmax_kernel<<<BATCH * SEQ, 256>>>();

    dim3 gPV(HDIM / 128, SEQ / 128, BATCH);
    pv_kernel<<<gPV, 256>>>(out);
}

// round 5
// speedup vs baseline: 2.0821x; 2.0821x over previous
#include <cuda_runtime.h>
#include <cuda_bf16.h>
#include <cstdint>

#define BATCH 4
#define SEQ   2048
#define EMB   1024
#define HDIM  1024
#define MROWS (BATCH*SEQ)

#define KCHUNK       16
#define ROW_HALVES   24                       // 16 data halves + 8 pad (48B pitch, conflict-free)
#define TILE_HALVES  (128*ROW_HALVES)         // 3072 halves = 6144 B
#define TILE_B       (TILE_HALVES*2)
#define STAGE_HALVES (4*TILE_HALVES)          // Ah, Al, Bh, Bl = 24576 B
#define STAGE_B      (STAGE_HALVES*2)
// total static smem: 2*STAGE_B = 49152 B = 48 KB exactly (static limit)

// ---------------- device scratch (allocation-free rule) ----------------
__device__ __nv_bfloat16 g_Xhi[(size_t)MROWS*EMB];
__device__ __nv_bfloat16 g_Xlo[(size_t)MROWS*EMB];
__device__ __nv_bfloat16 g_Whi[(size_t)3*HDIM*EMB];
__device__ __nv_bfloat16 g_Wlo[(size_t)3*HDIM*EMB];
__device__ __nv_bfloat16 g_Qhi[(size_t)MROWS*HDIM];
__device__ __nv_bfloat16 g_Qlo[(size_t)MROWS*HDIM];
__device__ __nv_bfloat16 g_Khi[(size_t)MROWS*HDIM];
__device__ __nv_bfloat16 g_Klo[(size_t)MROWS*HDIM];
__device__ __nv_bfloat16 g_Vthi[(size_t)BATCH*HDIM*SEQ];  // [b][d][s]
__device__ __nv_bfloat16 g_Vtlo[(size_t)BATCH*HDIM*SEQ];
__device__ float         g_S  [(size_t)BATCH*SEQ*SEQ];
__device__ __nv_bfloat16 g_Phi[(size_t)BATCH*SEQ*SEQ];
__device__ __nv_bfloat16 g_Plo[(size_t)BATCH*SEQ*SEQ];

// ---------------- helpers ----------------
__device__ __forceinline__ uint32_t smem_u32(const void* p) {
    uint32_t a;
    asm("{ .reg .u64 t; cvta.to.shared.u64 t, %1; cvt.u32.u64 %0, t; }" : "=r"(a) : "l"(p));
    return a;
}
__device__ __forceinline__ void cp16(uint32_t saddr, const void* g) {
    asm volatile("cp.async.cg.shared.global [%0], [%1], 16;" :: "r"(saddr), "l"(g));
}
#define CP_COMMIT() asm volatile("cp.async.commit_group;" ::: "memory")
#define CP_WAIT1()  asm volatile("cp.async.wait_group 1;" ::: "memory")
#define CP_WAIT0()  asm volatile("cp.async.wait_group 0;" ::: "memory")

#define MMA(c, a, b) \
    asm volatile("mma.sync.aligned.m16n8k16.row.col.f32.bf16.bf16.f32 " \
        "{%0,%1,%2,%3}, {%4,%5,%6,%7}, {%8,%9}, {%0,%1,%2,%3};" \
        : "+f"((c)[0]), "+f"((c)[1]), "+f"((c)[2]), "+f"((c)[3]) \
        : "r"((a)[0]), "r"((a)[1]), "r"((a)[2]), "r"((a)[3]), "r"((b)[0]), "r"((b)[1]))

__device__ __forceinline__ void split2(float x, uint16_t& h, uint16_t& l) {
    __nv_bfloat16 hb = __float2bfloat16(x);
    __nv_bfloat16 lb = __float2bfloat16(x - __bfloat162float(hb));
    h = __bfloat16_as_ushort(hb);
    l = __bfloat16_as_ushort(lb);
}
__device__ __forceinline__ uint32_t pack2(uint16_t a, uint16_t b) {
    return (uint32_t)a | ((uint32_t)b << 16);
}

// ---------------- split kernels ----------------
__global__ __launch_bounds__(256) void split_x_kernel(const float* __restrict__ src) {
    size_t i = ((size_t)blockIdx.x * 256 + threadIdx.x) * 4;
    float4 v = *(const float4*)(src + i);
    uint16_t h[4], l[4];
    split2(v.x, h[0], l[0]); split2(v.y, h[1], l[1]);
    split2(v.z, h[2], l[2]); split2(v.w, h[3], l[3]);
    *(uint2*)((uint16_t*)g_Xhi + i) = make_uint2(pack2(h[0], h[1]), pack2(h[2], h[3]));
    *(uint2*)((uint16_t*)g_Xlo + i) = make_uint2(pack2(l[0], l[1]), pack2(l[2], l[3]));
}
__global__ __launch_bounds__(256) void split_w_kernel(const float* __restrict__ src, int z) {
    size_t i = ((size_t)blockIdx.x * 256 + threadIdx.x) * 4;
    size_t off = (size_t)z * HDIM * EMB;
    float4 v = *(const float4*)(src + i);
    uint16_t h[4], l[4];
    split2(v.x, h[0], l[0]); split2(v.y, h[1], l[1]);
    split2(v.z, h[2], l[2]); split2(v.w, h[3], l[3]);
    *(uint2*)((uint16_t*)g_Whi + off + i) = make_uint2(pack2(h[0], h[1]), pack2(h[2], h[3]));
    *(uint2*)((uint16_t*)g_Wlo + off + i) = make_uint2(pack2(l[0], l[1]), pack2(l[2], l[3]));
}

// ---------------- stage load: 4 tiles of 128x16 bf16 via cp.async ----------------
__device__ __forceinline__ void load_stage(
    uint32_t sb, const __nv_bfloat16* __restrict__ Ah, const __nv_bfloat16* __restrict__ Al,
    const __nv_bfloat16* __restrict__ Bh, const __nv_bfloat16* __restrict__ Bl,
    int ldA, int ldB, int k0, int tid)
{
    const int row = tid >> 1, part = tid & 1;          // 256 threads = 256 16B-chunks/tile
    const uint32_t so = (uint32_t)(row * ROW_HALVES + part * 8) * 2;
    const size_t goA = (size_t)row * ldA + k0 + part * 8;
    const size_t goB = (size_t)row * ldB + k0 + part * 8;
    cp16(sb + 0 * TILE_B + so, Ah + goA);
    cp16(sb + 1 * TILE_B + so, Al + goA);
    cp16(sb + 2 * TILE_B + so, Bh + goB);
    cp16(sb + 3 * TILE_B + so, Bl + goB);
}

// ---------------- warp-MMA mainloop: acc += (Ah+Al)(Bh+Bl)^T, 3-pass split ----------------
// 128x128 CTA tile, 8 warps of 64x32, double-buffered cp.async stages.
__device__ __forceinline__ void gemm_mainloop(
    const __nv_bfloat16* __restrict__ Ah, const __nv_bfloat16* __restrict__ Al,
    const __nv_bfloat16* __restrict__ Bh, const __nv_bfloat16* __restrict__ Bl,
    int ldA, int ldB, int nChunks, float acc[4][4][4])
{
    __shared__ __align__(16) uint16_t sm[2 * STAGE_HALVES];   // 49152 B

    const int tid  = threadIdx.x;
    const int lane = tid & 31, warp = tid >> 5;
    const int wr = warp >> 2, wc = warp & 3;
    const uint32_t sbase = smem_u32(sm);

#pragma unroll
    for (int mt = 0; mt < 4; mt++)
#pragma unroll
        for (int nt = 0; nt < 4; nt++)
#pragma unroll
            for (int e = 0; e < 4; e++) acc[mt][nt][e] = 0.f;

    load_stage(sbase, Ah, Al, Bh, Bl, ldA, ldB, 0, tid);
    CP_COMMIT();

    const int arow = wr * 64 + (lane >> 2);
    const int brow = wc * 32 + (lane >> 2);
    const int kc   = (lane & 3) * 2;

    for (int ic = 0; ic < nChunks; ic++) {
        const int buf = ic & 1;
        if (ic + 1 < nChunks) {
            load_stage(sbase + (buf ^ 1) * STAGE_B, Ah, Al, Bh, Bl, ldA, ldB, (ic + 1) * KCHUNK, tid);
            CP_COMMIT();
            CP_WAIT1();
        } else {
            CP_WAIT0();
        }
        __syncthreads();

        const uint16_t* st = sm + buf * STAGE_HALVES;
        uint32_t a[4][4], bh[4][2], bl[4][2];
#pragma unroll
        for (int mt = 0; mt < 4; mt++) {
            const uint16_t* p = st + (arow + mt * 16) * ROW_HALVES + kc;          // Ah
            a[mt][0] = *(const uint32_t*)p;
            a[mt][1] = *(const uint32_t*)(p + 8 * ROW_HALVES);
            a[mt][2] = *(const uint32_t*)(p + 8);
            a[mt][3] = *(const uint32_t*)(p + 8 * ROW_HALVES + 8);
        }
#pragma unroll
        for (int nt = 0; nt < 4; nt++) {
            const uint16_t* p = st + 2 * TILE_HALVES + (brow + nt * 8) * ROW_HALVES + kc;  // Bh
            bh[nt][0] = *(const uint32_t*)p;
            bh[nt][1] = *(const uint32_t*)(p + 8);
            const uint16_t* q = st + 3 * TILE_HALVES + (brow + nt * 8) * ROW_HALVES + kc;  // Bl
            bl[nt][0] = *(const uint32_t*)q;
            bl[nt][1] = *(const uint32_t*)(q + 8);
        }
#pragma unroll
        for (int mt = 0; mt < 4; mt++)
#pragma unroll
            for (int nt = 0; nt < 4; nt++) MMA(acc[mt][nt], a[mt], bh[nt]);   // hi*hi
#pragma unroll
        for (int mt = 0; mt < 4; mt++)
#pragma unroll
            for (int nt = 0; nt < 4; nt++) MMA(acc[mt][nt], a[mt], bl[nt]);   // hi*lo
#pragma unroll
        for (int mt = 0; mt < 4; mt++) {
            const uint16_t* p = st + TILE_HALVES + (arow + mt * 16) * ROW_HALVES + kc;     // Al
            a[mt][0] = *(const uint32_t*)p;
            a[mt][1] = *(const uint32_t*)(p + 8 * ROW_HALVES);
            a[mt][2] = *(const uint32_t*)(p + 8);
            a[mt][3] = *(const uint32_t*)(p + 8 * ROW_HALVES + 8);
        }
#pragma unroll
        for (int mt = 0; mt < 4; mt++)
#pragma unroll
            for (int nt = 0; nt < 4; nt++) MMA(acc[mt][nt], a[mt], bh[nt]);   // lo*hi
        __syncthreads();
    }
}

// ---------------- kernel 1: QKV projection ----------------
// z==0 -> Q split; z==1 -> K split; z==2 -> V split, stored TRANSPOSED (Vt[b][d][s])
__global__ __launch_bounds__(256) void qkv_kernel(
    const float* __restrict__ bq, const float* __restrict__ bk, const float* __restrict__ bv)
{
    const int z = blockIdx.z;
    const int m0 = blockIdx.y * 128, n0 = blockIdx.x * 128;
    const __nv_bfloat16* Ah = g_Xhi + (size_t)m0 * EMB;
    const __nv_bfloat16* Al = g_Xlo + (size_t)m0 * EMB;
    const __nv_bfloat16* Bh = g_Whi + (size_t)z * HDIM * EMB + (size_t)n0 * EMB;
    const __nv_bfloat16* Bl = g_Wlo + (size_t)z * HDIM * EMB + (size_t)n0 * EMB;

    float acc[4][4][4];
    gemm_mainloop(Ah, Al, Bh, Bl, EMB, EMB, EMB / KCHUNK, acc);

    const float* bias = (z == 0) ? bq : (z == 1) ? bk : bv;
    const int tid = threadIdx.x;
    const int lane = tid & 31, warp = tid >> 5;
    const int wr = warp >> 2, wc = warp & 3;

    if (z < 2) {
        uint16_t* oh = (uint16_t*)(z ? g_Khi : g_Qhi);
        uint16_t* ol = (uint16_t*)(z ? g_Klo : g_Qlo);
#pragma unroll
        for (int mt = 0; mt < 4; mt++)
#pragma unroll
            for (int nt = 0; nt < 4; nt++) {
                int row0 = wr * 64 + mt * 16 + (lane >> 2);
                int col0 = wc * 32 + nt * 8 + (lane & 3) * 2;
                float b0 = __ldg(&bias[n0 + col0]);
                float b1 = __ldg(&bias[n0 + col0 + 1]);
#pragma unroll
                for (int h = 0; h < 2; h++) {
                    int row = row0 + 8 * h;
                    float v0 = acc[mt][nt][2 * h]     + b0;
                    float v1 = acc[mt][nt][2 * h + 1] + b1;
                    uint16_t h0, l0, h1, l1;
                    split2(v0, h0, l0); split2(v1, h1, l1);
                    size_t o = (size_t)(m0 + row) * HDIM + n0 + col0;
                    *(uint32_t*)(oh + o) = pack2(h0, h1);
                    *(uint32_t*)(ol + o) = pack2(l0, l1);
                }
            }
    } else {
        // V transposed: Vt[b][d][s]. u16 scatter; 8 lanes/col give 16B-contiguous runs.
        const int b = m0 >> 11;
        const int s0 = m0 & (SEQ - 1);
        uint16_t* vh = (uint16_t*)g_Vthi + ((size_t)b * HDIM + n0) * SEQ + s0;
        uint16_t* vl = (uint16_t*)g_Vtlo + ((size_t)b * HDIM + n0) * SEQ + s0;
#pragma unroll
        for (int mt = 0; mt < 4; mt++)
#pragma unroll
            for (int nt = 0; nt < 4; nt++) {
                int row0 = wr * 64 + mt * 16 + (lane >> 2);
                int col0 = wc * 32 + nt * 8 + (lane & 3) * 2;
                float b0 = __ldg(&bias[n0 + col0]);
                float b1 = __ldg(&bias[n0 + col0 + 1]);
#pragma unroll
                for (int h = 0; h < 2; h++) {
                    int row = row0 + 8 * h;         // s coordinate
                    uint16_t h0, l0, h1, l1;
                    split2(acc[mt][nt][2 * h]     + b0, h0, l0);
                    split2(acc[mt][nt][2 * h + 1] + b1, h1, l1);
                    vh[(size_t)col0 * SEQ + row]       = h0;
                    vl[(size_t)col0 * SEQ + row]       = l0;
                    vh[(size_t)(col0 + 1) * SEQ + row] = h1;
                    vl[(size_t)(col0 + 1) * SEQ + row] = l1;
                }
            }
    }
}

// ---------------- kernel 2: causal scores ----------------
__global__ __launch_bounds__(256) void scores_kernel()
{
    if (blockIdx.x > blockIdx.y) return;   // fully-masked tile
    const int b = blockIdx.z;
    const int m0 = blockIdx.y * 128, n0 = blockIdx.x * 128;
    const __nv_bfloat16* Ah = g_Qhi + ((size_t)(b * SEQ + m0)) * HDIM;
    const __nv_bfloat16* Al = g_Qlo + ((size_t)(b * SEQ + m0)) * HDIM;
    const __nv_bfloat16* Bh = g_Khi + ((size_t)(b * SEQ + n0)) * HDIM;
    const __nv_bfloat16* Bl = g_Klo + ((size_t)(b * SEQ + n0)) * HDIM;

    float acc[4][4][4];
    gemm_mainloop(Ah, Al, Bh, Bl, HDIM, HDIM, HDIM / KCHUNK, acc);

    const int tid = threadIdx.x;
    const int lane = tid & 31, warp = tid >> 5;
    const int wr = warp >> 2, wc = warp & 3;
    const float scale = 0.03125f;   // 1/sqrt(1024)
    float* S = g_S + (size_t)b * SEQ * SEQ;
#pragma unroll
    for (int mt = 0; mt < 4; mt++)
#pragma unroll
        for (int nt = 0; nt < 4; nt++) {
            int row0 = wr * 64 + mt * 16 + (lane >> 2);
            int col0 = wc * 32 + nt * 8 + (lane & 3) * 2;
#pragma unroll
            for (int h = 0; h < 2; h++) {
                int row = row0 + 8 * h;
                float2 v = { acc[mt][nt][2*h] * scale, acc[mt][nt][2*h+1] * scale };
                *(float2*)&S[(size_t)(m0 + row) * SEQ + n0 + col0] = v;
            }
        }
}

// ---------------- kernel 3: softmax -> split P with exact-zero causal tail ----------------
__global__ __launch_bounds__(256) void softmax_kernel()
{
    const int rowid = blockIdx.x;
    const int q = rowid & (SEQ - 1);
    const float* s = g_S + (size_t)rowid * SEQ;
    uint16_t* ph = (uint16_t*)g_Phi + (size_t)rowid * SEQ;
    uint16_t* pl = (uint16_t*)g_Plo + (size_t)rowid * SEQ;
    const int valid = q + 1;
    const int tid = threadIdx.x;
    __shared__ float red[256];

    float sv[8];
    float mx = -3.0e38f;
    {
        int n = 0;
        for (int i = tid; i < valid; i += 256, n++) { sv[n] = s[i]; mx = fmaxf(mx, sv[n]); }
    }
    red[tid] = mx;
    __syncthreads();
    for (int st = 128; st > 0; st >>= 1) {
        if (tid < st) red[tid] = fmaxf(red[tid], red[tid + st]);
        __syncthreads();
    }
    mx = red[0];
    __syncthreads();

    float ev[8];
    float sum = 0.f;
    {
        int n = 0;
        for (int i = tid; i < valid; i += 256, n++) { ev[n] = __expf(sv[n] - mx); sum += ev[n]; }
    }
    red[tid] = sum;
    __syncthreads();
    for (int st = 128; st > 0; st >>= 1) {
        if (tid < st) red[tid] += red[tid + st];
        __syncthreads();
    }
    const float inv = 1.0f / red[0];

    {
        int n = 0;
        for (int i = tid; i < SEQ; i += 256, n++) {
            if (i < valid) {
                uint16_t h, l;
                split2(ev[n] * inv, h, l);
                ph[i] = h; pl[i] = l;
            } else {
                ph[i] = 0; pl[i] = 0;
            }
        }
    }
}

// ---------------- kernel 4: O = P V (causal-bounded K loop) ----------------
__global__ __launch_bounds__(256) void pv_kernel(float* __restrict__ O)
{
    const int b = blockIdx.z;
    const int m0 = blockIdx.y * 128, n0 = blockIdx.x * 128;
    const __nv_bfloat16* Ah = g_Phi  + (size_t)b * SEQ * SEQ + (size_t)m0 * SEQ;
    const __nv_bfloat16* Al = g_Plo  + (size_t)b * SEQ * SEQ + (size_t)m0 * SEQ;
    const __nv_bfloat16* Bh = g_Vthi + ((size_t)b * HDIM + n0) * SEQ;
    const __nv_bfloat16* Bl = g_Vtlo + ((size_t)b * HDIM + n0) * SEQ;
    const int nChunks = m0 / KCHUNK + 8;   // K in [0, m0+128)

    float acc[4][4][4];
    gemm_mainloop(Ah, Al, Bh, Bl, SEQ, SEQ, nChunks, acc);

    const int tid = threadIdx.x;
    const int lane = tid & 31, warp = tid >> 5;
    const int wr = warp >> 2, wc = warp & 3;
    float* C = O + (size_t)b * SEQ * HDIM;
#pragma unroll
    for (int mt = 0; mt < 4; mt++)
#pragma unroll
        for (int nt = 0; nt < 4; nt++) {
            int row0 = wr * 64 + mt * 16 + (lane >> 2);
            int col0 = wc * 32 + nt * 8 + (lane & 3) * 2;
#pragma unroll
            for (int h = 0; h < 2; h++) {
                int row = row0 + 8 * h;
                float2 v = { acc[mt][nt][2*h], acc[mt][nt][2*h+1] };
                *(float2*)&C[(size_t)(m0 + row) * HDIM + n0 + col0] = v;
            }
        }
}

// ---------------- launch: kernel launches ONLY ----------------
extern "C" void kernel_launch(void* const* d_in, const int* in_sizes, int n_in,
                              void* d_out, int out_size)
{
    (void)in_sizes; (void)n_in; (void)out_size;
    const float* X  = (const float*)d_in[0];
    const float* Wq = (const float*)d_in[1];
    const float* bq = (const float*)d_in[2];
    const float* Wk = (const float*)d_in[3];
    const float* bk = (const float*)d_in[4];
    const float* Wv = (const float*)d_in[5];
    const float* bv = (const float*)d_in[6];
    float* out = (float*)d_out;

    split_x_kernel<<<(MROWS * EMB) / 1024, 256>>>(X);
    split_w_kernel<<<(HDIM * EMB) / 1024, 256>>>(Wq, 0);
    split_w_kernel<<<(HDIM * EMB) / 1024, 256>>>(Wk, 1);
    split_w_kernel<<<(HDIM * EMB) / 1024, 256>>>(Wv, 2);

    qkv_kernel<<<dim3(HDIM / 128, MROWS / 128, 3), 256>>>(bq, bk, bv);
    scores_kernel<<<dim3(SEQ / 128, SEQ / 128, BATCH), 256>>>();
    softmax_kernel<<<MROWS, 256>>>();
    pv_kernel<<<dim3(HDIM / 128, SEQ / 128, BATCH), 256>>>(out);
}